// round 15
// baseline (speedup 1.0000x reference)
#include <cuda_runtime.h>
#include <cuda_bf16.h>
#include <math.h>
#include <stdint.h>

#define N_NODES 50000
#define N_EDGES 800000
#define DIM     64
#define N_LAYERS 5
#define N_STAGES (N_LAYERS * 3)

#define SCAN_BLK  512
#define SCAN_NBLK ((N_NODES + SCAN_BLK - 1) / SCAN_BLK)   // 98
#define NBINS 256

#define FLAG_AGG (1u << 30)
#define FLAG_INC (2u << 30)
#define VAL_MASK (FLAG_AGG - 1u)

// Scratch (no allocations -> __device__ globals).
// Replay contract: g_hb rewritten by k_count_x; g_wbh/g_wbl by k_fill_w;
// g_deg/g_sstate/g_dhist re-zeroed by k_fill_w; g_cur by k_scan;
// g_dcur set by k_order_off; g_pooled by k_final. .bss zero on first run.
__device__ __align__(16) __nv_bfloat16 g_hb[N_NODES * DIM];
__device__ __align__(16) __nv_bfloat16 g_aggb[N_NODES * DIM];
__device__ __align__(16) __nv_bfloat16 g_wbh[N_STAGES * DIM * DIM];
__device__ __align__(16) __nv_bfloat16 g_wbl[N_STAGES * DIM * DIM];
__device__ float    g_pooled[N_LAYERS * DIM];
__device__ int      g_deg[N_NODES];
__device__ int      g_cur[N_NODES];
__device__ int      g_off[N_NODES + 1];
__device__ int      g_csr[N_EDGES];
__device__ int      g_order[N_NODES];
__device__ int      g_dhist[NBINS];
__device__ int      g_dcur[NBINS];
__device__ unsigned g_sstate[SCAN_NBLK];

__device__ __forceinline__ uint32_t pack_bf2(float a, float b)
{
    return (uint32_t)__bfloat16_as_ushort(__float2bfloat16(a))
         | ((uint32_t)__bfloat16_as_ushort(__float2bfloat16(b)) << 16);
}

// ---------------------------------------------------------------------------
// idx0: histogram of dst + convert x -> bf16 h
// ---------------------------------------------------------------------------
__global__ void k_count_x(const int* __restrict__ dst, const float2* __restrict__ x2)
{
    int i = blockIdx.x * blockDim.x + threadIdx.x;
    if (i < N_EDGES)
        atomicAdd(&g_deg[dst[i]], 1);
    if (i < N_NODES * DIM / 2) {
        float2 v = __ldg(&x2[i]);
        reinterpret_cast<uint32_t*>(g_hb)[i] = pack_bf2(v.x, v.y);
    }
}

// ---------------------------------------------------------------------------
// idx1: single-pass exclusive scan (decoupled lookback). Zeroes g_cur.
// Also accumulates the degree histogram (smem-aggregated).
// ---------------------------------------------------------------------------
__global__ void k_scan()
{
    __shared__ int sh[SCAN_BLK];
    __shared__ int s_prefix;
    __shared__ int hist[NBINS];
    int tid = threadIdx.x;
    int b   = blockIdx.x;
    int i   = b * SCAN_BLK + tid;
    int v   = (i < N_NODES) ? g_deg[i] : 0;

    if (tid < NBINS) hist[tid] = 0;
    sh[tid] = v;
    __syncthreads();
    if (i < N_NODES)
        atomicAdd(&hist[v < NBINS ? v : NBINS - 1], 1);
    for (int o = 1; o < SCAN_BLK; o <<= 1) {
        int t = (tid >= o) ? sh[tid - o] : 0;
        __syncthreads();
        sh[tid] += t;
        __syncthreads();
    }
    int total = sh[SCAN_BLK - 1];

    if (tid < 32) {
        int lane = tid;
        if (lane == 0) {
            unsigned pub = (b == 0) ? (FLAG_INC | (unsigned)total)
                                    : (FLAG_AGG | (unsigned)total);
            atomicExch(&g_sstate[b], pub);
        }
        __syncwarp();

        int run = 0;
        if (b > 0) {
            int j = b - 1;
            while (true) {
                int idx = j - lane;
                bool have = (idx >= 0);
                unsigned s = 0;
                if (have) {
                    do { s = atomicAdd(&g_sstate[idx], 0u); } while (s < FLAG_AGG);
                }
                unsigned incmask = __ballot_sync(0xffffffffu, have && (s >= FLAG_INC));
                int firstinc = incmask ? (__ffs(incmask) - 1) : 32;
                unsigned contrib = (have && lane <= firstinc) ? (s & VAL_MASK) : 0u;
                for (int o = 16; o > 0; o >>= 1)
                    contrib += __shfl_down_sync(0xffffffffu, contrib, o);
                contrib = __shfl_sync(0xffffffffu, contrib, 0);
                run += (int)contrib;
                if (incmask) break;
                j -= 32;
            }
            if (lane == 0)
                atomicExch(&g_sstate[b], FLAG_INC | (unsigned)(run + total));
        }
        if (lane == 0) s_prefix = run;
    }
    __syncthreads();

    if (i < N_NODES) {
        g_off[i] = s_prefix + (sh[tid] - v);
        g_cur[i] = 0;
    }
    if (b == 0 && tid == 0) g_off[N_NODES] = N_EDGES;
    if (tid < NBINS && hist[tid] > 0)
        atomicAdd(&g_dhist[tid], hist[tid]);
}

// ---------------------------------------------------------------------------
// idx2: exclusive prefix over 256 degree bins -> g_dcur (scatter cursors)
// ---------------------------------------------------------------------------
__global__ void k_order_off()
{
    __shared__ int sh[NBINS];
    int tid = threadIdx.x;
    int v = g_dhist[tid];
    sh[tid] = v;
    __syncthreads();
    for (int o = 1; o < NBINS; o <<= 1) {
        int t = (tid >= o) ? sh[tid - o] : 0;
        __syncthreads();
        sh[tid] += t;
        __syncthreads();
    }
    g_dcur[tid] = sh[tid] - v;   // exclusive
}

// ---------------------------------------------------------------------------
// idx3: scatter nodes into degree-sorted order
// ---------------------------------------------------------------------------
__global__ void k_order()
{
    int i = blockIdx.x * blockDim.x + threadIdx.x;
    if (i < N_NODES) {
        int d = g_deg[i];
        int bin = d < NBINS ? d : NBINS - 1;
        int pos = atomicAdd(&g_dcur[bin], 1);
        g_order[pos] = i;
    }
}

// ---------------------------------------------------------------------------
// idx4: bucket-fill + precompute weight hi/lo split (B[n][k] swizzled).
// Re-zeroes g_deg/g_sstate/g_dhist for next replay.
// ---------------------------------------------------------------------------
__global__ void k_fill_w(const int* __restrict__ src, const int* __restrict__ dst,
                         const float* __restrict__ W)
{
    int e = blockIdx.x * blockDim.x + threadIdx.x;
    if (e < N_EDGES) {
        int d = dst[e];
        int p = atomicAdd(&g_cur[d], 1);
        g_csr[g_off[d] + p] = src[e];
    }
    if (e < N_STAGES * DIM * DIM) {
        int stage = e >> 12;
        int idx   = e & 4095;
        int k = idx >> 6, n = idx & 63;
        float w = __ldg(&W[e]);
        __nv_bfloat16 wh = __float2bfloat16(w);
        float wl = w - __bfloat162float(wh);
        uint32_t off = (uint32_t)n * 64 + ((((uint32_t)k >> 3) ^ (n & 7)) << 3) + (k & 7);
        g_wbh[stage * 4096 + off] = wh;
        g_wbl[stage * 4096 + off] = __float2bfloat16(wl);
    }
    if (e < N_NODES) g_deg[e] = 0;
    if (e < SCAN_NBLK) g_sstate[e] = 0;
    if (e >= N_EDGES - NBINS) g_dhist[e - (N_EDGES - NBINS)] = 0;
}

// ---------------------------------------------------------------------------
// Gather v5: v3 body (8 thr/node, 16B, 4-wide unroll, HADD2) but nodes
// processed in degree-sorted order -> uniform-degree warps, no divergence.
// ---------------------------------------------------------------------------
__device__ __forceinline__ uint32_t hadd2u(uint32_t a, uint32_t b)
{
    __nv_bfloat162 r = __hadd2(*reinterpret_cast<__nv_bfloat162*>(&a),
                               *reinterpret_cast<__nv_bfloat162*>(&b));
    return *reinterpret_cast<uint32_t*>(&r);
}
__device__ __forceinline__ uint4 hadd2q(uint4 a, uint4 b)
{
    return make_uint4(hadd2u(a.x, b.x), hadd2u(a.y, b.y),
                      hadd2u(a.z, b.z), hadd2u(a.w, b.w));
}

__global__ void k_gather_b()
{
    int idx = blockIdx.x * blockDim.x + threadIdx.x;
    if (idx >= N_NODES * 8) return;
    int slot = idx >> 3;
    int c = idx & 7;

    int v = __ldg(&g_order[slot]);

    const uint4* hb = reinterpret_cast<const uint4*>(g_hb);

    uint4 A0 = __ldg(&hb[v * 8 + c]);
    uint4 A1 = make_uint4(0, 0, 0, 0);
    uint4 A2 = make_uint4(0, 0, 0, 0);
    uint4 A3 = make_uint4(0, 0, 0, 0);

    int j = g_off[v];
    int end = g_off[v + 1];

    for (; j + 4 <= end; j += 4) {
        int u0 = __ldg(&g_csr[j]);
        int u1 = __ldg(&g_csr[j + 1]);
        int u2 = __ldg(&g_csr[j + 2]);
        int u3 = __ldg(&g_csr[j + 3]);
        uint4 q0 = __ldg(&hb[u0 * 8 + c]);
        uint4 q1 = __ldg(&hb[u1 * 8 + c]);
        uint4 q2 = __ldg(&hb[u2 * 8 + c]);
        uint4 q3 = __ldg(&hb[u3 * 8 + c]);
        A0 = hadd2q(A0, q0);
        A1 = hadd2q(A1, q1);
        A2 = hadd2q(A2, q2);
        A3 = hadd2q(A3, q3);
    }
    for (; j < end; j++)
        A0 = hadd2q(A0, __ldg(&hb[__ldg(&g_csr[j]) * 8 + c]));

    A0 = hadd2q(hadd2q(A0, A1), hadd2q(A2, A3));
    reinterpret_cast<uint4*>(g_aggb)[v * 8 + c] = A0;
}

// ---------------------------------------------------------------------------
// HMMA MLP, 2-term (unchanged — measured, rel_err 0.0)
// ---------------------------------------------------------------------------
#define TILE_M 128
#define MLP_GRID ((N_NODES + TILE_M - 1) / TILE_M)   // 391

struct __align__(16) H2Smem {
    __nv_bfloat16 a[TILE_M * 64];
    __nv_bfloat16 bh[64 * 64];
    __nv_bfloat16 bl[64 * 64];
    float pool[DIM];
};

__device__ __forceinline__ uint32_t smem_u32(const void* p)
{
    uint32_t a;
    asm("{ .reg .u64 t; cvta.to.shared.u64 t, %1; cvt.u32.u64 %0, t; }"
        : "=r"(a) : "l"(p));
    return a;
}
__device__ __forceinline__ void ldsm4(uint32_t* r, uint32_t addr)
{
    asm volatile("ldmatrix.sync.aligned.m8n8.x4.shared.b16 {%0,%1,%2,%3}, [%4];"
                 : "=r"(r[0]), "=r"(r[1]), "=r"(r[2]), "=r"(r[3]) : "r"(addr));
}
__device__ __forceinline__ void ldsm2(uint32_t* r, uint32_t addr)
{
    asm volatile("ldmatrix.sync.aligned.m8n8.x2.shared.b16 {%0,%1}, [%2];"
                 : "=r"(r[0]), "=r"(r[1]) : "r"(addr));
}
__device__ __forceinline__ void mma16816(float* d, const uint32_t* a, const uint32_t* b)
{
    asm volatile("mma.sync.aligned.m16n8k16.row.col.f32.bf16.bf16.f32 "
                 "{%0,%1,%2,%3}, {%4,%5,%6,%7}, {%8,%9}, {%0,%1,%2,%3};"
                 : "+f"(d[0]), "+f"(d[1]), "+f"(d[2]), "+f"(d[3])
                 : "r"(a[0]), "r"(a[1]), "r"(a[2]), "r"(a[3]),
                   "r"(b[0]), "r"(b[1]));
}

__global__ __launch_bounds__(256) void k_mlp_h2(int layer)
{
    __shared__ H2Smem sm;

    int tid  = threadIdx.x;
    int lane = tid & 31;
    int w    = tid >> 5;
    int m0   = w * 16;
    int blockBase = blockIdx.x * TILE_M;

    char* a_c = reinterpret_cast<char*>(sm.a);

    {
        const uint4* agg4 = reinterpret_cast<const uint4*>(g_aggb);
#pragma unroll
        for (int r = 0; r < 4; r++) {
            int j = tid + 256 * r;
            int row = j >> 3, ch = j & 7;
            int node = blockBase + row;
            uint4 val = make_uint4(0, 0, 0, 0);
            if (node < N_NODES) val = __ldg(&agg4[node * 8 + ch]);
            uint32_t off = (uint32_t)row * 128 + ((uint32_t)(ch ^ (row & 7)) << 4);
            *reinterpret_cast<uint4*>(a_c + off) = val;
        }
    }
    if (tid < DIM) sm.pool[tid] = 0.f;

    uint32_t a_base  = smem_u32(sm.a);
    uint32_t bh_base = smem_u32(sm.bh);
    uint32_t bl_base = smem_u32(sm.bl);
    int r0 = m0 + (lane >> 2);
    int r1 = r0 + 8;

    for (int s = 0; s < 3; s++) {
        {
            const uint4* wh4 = reinterpret_cast<const uint4*>(
                g_wbh + (size_t)(layer * 3 + s) * 4096);
            const uint4* wl4 = reinterpret_cast<const uint4*>(
                g_wbl + (size_t)(layer * 3 + s) * 4096);
            uint4* sh = reinterpret_cast<uint4*>(sm.bh);
            uint4* sl = reinterpret_cast<uint4*>(sm.bl);
            sh[tid]       = __ldg(&wh4[tid]);
            sh[tid + 256] = __ldg(&wh4[tid + 256]);
            sl[tid]       = __ldg(&wl4[tid]);
            sl[tid + 256] = __ldg(&wl4[tid + 256]);
        }
        __syncthreads();

        float acc[8][4];
#pragma unroll
        for (int nt = 0; nt < 8; nt++)
#pragma unroll
            for (int q = 0; q < 4; q++) acc[nt][q] = 0.f;

#pragma unroll
        for (int kk = 0; kk < 4; kk++) {
            int arow = m0 + (lane & 15);
            uint32_t achunk = (uint32_t)(kk * 2 + (lane >> 4));
            uint32_t aoff = (uint32_t)arow * 128 + ((achunk ^ (arow & 7)) << 4);
            uint32_t aa[4];
            ldsm4(aa, a_base + aoff);

            int brow_l = lane & 7;
            uint32_t bchunk = (uint32_t)(kk * 2 + ((lane >> 3) & 1));
#pragma unroll
            for (int nt = 0; nt < 8; nt++) {
                int brow = nt * 8 + brow_l;
                uint32_t boff = (uint32_t)brow * 128 + ((bchunk ^ (brow & 7)) << 4);
                uint32_t bh[2], bl[2];
                ldsm2(bh, bh_base + boff);
                ldsm2(bl, bl_base + boff);
                mma16816(acc[nt], aa, bh);
                mma16816(acc[nt], aa, bl);
            }
        }
        __syncthreads();

        if (s < 2) {
#pragma unroll
            for (int nt = 0; nt < 8; nt++) {
                float v00 = fmaxf(acc[nt][0], 0.f);
                float v01 = fmaxf(acc[nt][1], 0.f);
                float v10 = fmaxf(acc[nt][2], 0.f);
                float v11 = fmaxf(acc[nt][3], 0.f);
                int p = nt * 4 + (lane & 3);
                uint32_t off0 = (uint32_t)r0 * 128 + (((uint32_t)(p >> 2) ^ (r0 & 7)) << 4) + (p & 3) * 4;
                uint32_t off1 = (uint32_t)r1 * 128 + (((uint32_t)(p >> 2) ^ (r1 & 7)) << 4) + (p & 3) * 4;
                *reinterpret_cast<uint32_t*>(a_c + off0) = pack_bf2(v00, v01);
                *reinterpret_cast<uint32_t*>(a_c + off1) = pack_bf2(v10, v11);
            }
            __syncthreads();
        } else {
            int node0 = blockBase + r0;
            int node1 = blockBase + r1;
            uint32_t* hb32 = reinterpret_cast<uint32_t*>(g_hb);
#pragma unroll
            for (int nt = 0; nt < 8; nt++) {
                float v00 = fmaxf(acc[nt][0], 0.f);
                float v01 = fmaxf(acc[nt][1], 0.f);
                float v10 = fmaxf(acc[nt][2], 0.f);
                float v11 = fmaxf(acc[nt][3], 0.f);
                int p = nt * 4 + (lane & 3);
                if (node0 < N_NODES) hb32[node0 * 32 + p] = pack_bf2(v00, v01);
                if (node1 < N_NODES) hb32[node1 * 32 + p] = pack_bf2(v10, v11);
                float s0 = v00 + v10, s1 = v01 + v11;
                s0 += __shfl_xor_sync(0xffffffffu, s0, 16);
                s0 += __shfl_xor_sync(0xffffffffu, s0, 8);
                s0 += __shfl_xor_sync(0xffffffffu, s0, 4);
                s1 += __shfl_xor_sync(0xffffffffu, s1, 16);
                s1 += __shfl_xor_sync(0xffffffffu, s1, 8);
                s1 += __shfl_xor_sync(0xffffffffu, s1, 4);
                if ((lane >> 2) == 0) {
                    int c0 = nt * 8 + (lane & 3) * 2;
                    atomicAdd(&sm.pool[c0],     s0);
                    atomicAdd(&sm.pool[c0 + 1], s1);
                }
            }
            __syncthreads();
            if (tid < DIM)
                atomicAdd(&g_pooled[layer * DIM + tid], sm.pool[tid]);
        }
    }
}

// ---------------------------------------------------------------------------
// Final: out = sigmoid( sum_l dot(pooled_l / N, Wl_l) ); re-zero g_pooled
// ---------------------------------------------------------------------------
__global__ void k_final(const float* __restrict__ Wl, float* __restrict__ out)
{
    __shared__ float red[128];
    int tid = threadIdx.x;
    float s = 0.0f;
    for (int i = tid; i < N_LAYERS * DIM; i += 128)
        s += g_pooled[i] * Wl[i];
    red[tid] = s;
    __syncthreads();
    for (int i = tid; i < N_LAYERS * DIM; i += 128)
        g_pooled[i] = 0.0f;
    for (int o = 64; o > 0; o >>= 1) {
        if (tid < o) red[tid] += red[tid + o];
        __syncthreads();
    }
    if (tid == 0) {
        float v = red[0] / (float)N_NODES;
        out[0] = 1.0f / (1.0f + expf(-v));
    }
}

// ---------------------------------------------------------------------------
// Launch
// ---------------------------------------------------------------------------
extern "C" void kernel_launch(void* const* d_in, const int* in_sizes, int n_in,
                              void* d_out, int out_size)
{
    const float* x   = (const float*)d_in[0];
    const float* W   = (const float*)d_in[1];
    const float* Wl  = (const float*)d_in[2];
    const int*   src = (const int*)d_in[3];
    const int*   dst = (const int*)d_in[4];
    float*       out = (float*)d_out;

    (void)in_sizes; (void)n_in; (void)out_size;

    k_count_x<<<(N_NODES * DIM / 2 + 255) / 256, 256>>>(dst, (const float2*)x); // idx0
    k_scan<<<SCAN_NBLK, SCAN_BLK>>>();                                          // idx1
    k_order_off<<<1, NBINS>>>();                                                // idx2
    k_order<<<(N_NODES + 255) / 256, 256>>>();                                  // idx3
    k_fill_w<<<(N_EDGES + 255) / 256, 256>>>(src, dst, W);                      // idx4

    int gather_blocks = (N_NODES * 8 + 255) / 256;

    for (int l = 0; l < N_LAYERS; l++) {
        k_gather_b<<<gather_blocks, 256>>>();
        k_mlp_h2<<<MLP_GRID, 256>>>(l);
    }
    k_final<<<1, 128>>>(Wl, out);
}

// round 16
// speedup vs baseline: 1.0632x; 1.0632x over previous
#include <cuda_runtime.h>
#include <cuda_bf16.h>
#include <math.h>
#include <stdint.h>

#define N_NODES 50000
#define N_EDGES 800000
#define DIM     64
#define N_LAYERS 5
#define N_STAGES (N_LAYERS * 3)

#define SCAN_BLK  512
#define SCAN_NBLK ((N_NODES + SCAN_BLK - 1) / SCAN_BLK)   // 98

#define FLAG_AGG (1u << 30)
#define FLAG_INC (2u << 30)
#define VAL_MASK (FLAG_AGG - 1u)

#define EQ (N_EDGES / 4)   // 200000, edge-quarter stride for k_fill_w

// Scratch (no allocations -> __device__ globals).
// Replay contract: g_hb rewritten by k_count_x; g_wbh/g_wbl by k_fill_w;
// g_deg/g_sstate re-zeroed by k_fill_w; g_cur by k_scan; g_pooled by k_final.
__device__ __align__(16) __nv_bfloat16 g_hb[N_NODES * DIM];
__device__ __align__(16) __nv_bfloat16 g_aggb[N_NODES * DIM];
__device__ __align__(16) __nv_bfloat16 g_wbh[N_STAGES * DIM * DIM];
__device__ __align__(16) __nv_bfloat16 g_wbl[N_STAGES * DIM * DIM];
__device__ float    g_pooled[N_LAYERS * DIM];
__device__ int      g_deg[N_NODES];
__device__ int      g_cur[N_NODES];
__device__ int      g_off[N_NODES + 1];
__device__ int      g_csr[N_EDGES];
__device__ unsigned g_sstate[SCAN_NBLK];

__device__ __forceinline__ uint32_t pack_bf2(float a, float b)
{
    return (uint32_t)__bfloat16_as_ushort(__float2bfloat16(a))
         | ((uint32_t)__bfloat16_as_ushort(__float2bfloat16(b)) << 16);
}

// ---------------------------------------------------------------------------
// idx0: histogram of dst + convert x -> bf16 h
// ---------------------------------------------------------------------------
__global__ void k_count_x(const int* __restrict__ dst, const float2* __restrict__ x2)
{
    int i = blockIdx.x * blockDim.x + threadIdx.x;
    if (i < N_EDGES)
        atomicAdd(&g_deg[dst[i]], 1);
    if (i < N_NODES * DIM / 2) {
        float2 v = __ldg(&x2[i]);
        reinterpret_cast<uint32_t*>(g_hb)[i] = pack_bf2(v.x, v.y);
    }
}

// ---------------------------------------------------------------------------
// idx1: single-pass exclusive scan (decoupled lookback). Zeroes g_cur.
// ---------------------------------------------------------------------------
__global__ void k_scan()
{
    __shared__ int sh[SCAN_BLK];
    __shared__ int s_prefix;
    int tid = threadIdx.x;
    int b   = blockIdx.x;
    int i   = b * SCAN_BLK + tid;
    int v   = (i < N_NODES) ? g_deg[i] : 0;

    sh[tid] = v;
    __syncthreads();
    for (int o = 1; o < SCAN_BLK; o <<= 1) {
        int t = (tid >= o) ? sh[tid - o] : 0;
        __syncthreads();
        sh[tid] += t;
        __syncthreads();
    }
    int total = sh[SCAN_BLK - 1];

    if (tid < 32) {
        int lane = tid;
        if (lane == 0) {
            unsigned pub = (b == 0) ? (FLAG_INC | (unsigned)total)
                                    : (FLAG_AGG | (unsigned)total);
            atomicExch(&g_sstate[b], pub);
        }
        __syncwarp();

        int run = 0;
        if (b > 0) {
            int j = b - 1;
            while (true) {
                int idx = j - lane;
                bool have = (idx >= 0);
                unsigned s = 0;
                if (have) {
                    do { s = atomicAdd(&g_sstate[idx], 0u); } while (s < FLAG_AGG);
                }
                unsigned incmask = __ballot_sync(0xffffffffu, have && (s >= FLAG_INC));
                int firstinc = incmask ? (__ffs(incmask) - 1) : 32;
                unsigned contrib = (have && lane <= firstinc) ? (s & VAL_MASK) : 0u;
                for (int o = 16; o > 0; o >>= 1)
                    contrib += __shfl_down_sync(0xffffffffu, contrib, o);
                contrib = __shfl_sync(0xffffffffu, contrib, 0);
                run += (int)contrib;
                if (incmask) break;
                j -= 32;
            }
            if (lane == 0)
                atomicExch(&g_sstate[b], FLAG_INC | (unsigned)(run + total));
        }
        if (lane == 0) s_prefix = run;
    }
    __syncthreads();

    if (i < N_NODES) {
        g_off[i] = s_prefix + (sh[tid] - v);
        g_cur[i] = 0;
    }
    if (b == 0 && tid == 0) g_off[N_NODES] = N_EDGES;
}

// ---------------------------------------------------------------------------
// idx2: bucket-fill (4 edges/thread, strided -> 4 atomics in flight)
// + precompute weight hi/lo split. Re-zeroes g_deg/g_sstate for next replay.
// ---------------------------------------------------------------------------
__global__ void k_fill_w(const int* __restrict__ src, const int* __restrict__ dst,
                         const float* __restrict__ W)
{
    int t = blockIdx.x * blockDim.x + threadIdx.x;
    if (t < EQ) {
        int e0 = t, e1 = t + EQ, e2 = t + 2 * EQ, e3 = t + 3 * EQ;
        int d0 = __ldg(&dst[e0]);
        int d1 = __ldg(&dst[e1]);
        int d2 = __ldg(&dst[e2]);
        int d3 = __ldg(&dst[e3]);
        int s0 = __ldg(&src[e0]);
        int s1 = __ldg(&src[e1]);
        int s2 = __ldg(&src[e2]);
        int s3 = __ldg(&src[e3]);
        int o0 = __ldg(&g_off[d0]);
        int o1 = __ldg(&g_off[d1]);
        int o2 = __ldg(&g_off[d2]);
        int o3 = __ldg(&g_off[d3]);
        int p0 = atomicAdd(&g_cur[d0], 1);
        int p1 = atomicAdd(&g_cur[d1], 1);
        int p2 = atomicAdd(&g_cur[d2], 1);
        int p3 = atomicAdd(&g_cur[d3], 1);
        g_csr[o0 + p0] = s0;
        g_csr[o1 + p1] = s1;
        g_csr[o2 + p2] = s2;
        g_csr[o3 + p3] = s3;
    }
    if (t < N_STAGES * DIM * DIM) {
        int stage = t >> 12;
        int idx   = t & 4095;
        int k = idx >> 6, n = idx & 63;
        float w = __ldg(&W[t]);
        __nv_bfloat16 wh = __float2bfloat16(w);
        float wl = w - __bfloat162float(wh);
        uint32_t off = (uint32_t)n * 64 + ((((uint32_t)k >> 3) ^ (n & 7)) << 3) + (k & 7);
        g_wbh[stage * 4096 + off] = wh;
        g_wbl[stage * 4096 + off] = __float2bfloat16(wl);
    }
    if (t < N_NODES) g_deg[t] = 0;
    if (t < SCAN_NBLK) g_sstate[t] = 0;
}

// ---------------------------------------------------------------------------
// Gather v3 (R13 best): bf16 HADD2, 8 thr/node x 16B, 4-wide neighbor unroll.
// ---------------------------------------------------------------------------
__device__ __forceinline__ uint32_t hadd2u(uint32_t a, uint32_t b)
{
    __nv_bfloat162 r = __hadd2(*reinterpret_cast<__nv_bfloat162*>(&a),
                               *reinterpret_cast<__nv_bfloat162*>(&b));
    return *reinterpret_cast<uint32_t*>(&r);
}
__device__ __forceinline__ uint4 hadd2q(uint4 a, uint4 b)
{
    return make_uint4(hadd2u(a.x, b.x), hadd2u(a.y, b.y),
                      hadd2u(a.z, b.z), hadd2u(a.w, b.w));
}

__global__ void k_gather_b()
{
    int idx = blockIdx.x * blockDim.x + threadIdx.x;
    if (idx >= N_NODES * 8) return;
    int v = idx >> 3;
    int c = idx & 7;

    const uint4* hb = reinterpret_cast<const uint4*>(g_hb);

    uint4 A0 = __ldg(&hb[v * 8 + c]);
    uint4 A1 = make_uint4(0, 0, 0, 0);
    uint4 A2 = make_uint4(0, 0, 0, 0);
    uint4 A3 = make_uint4(0, 0, 0, 0);

    int j = g_off[v];
    int end = g_off[v + 1];

    for (; j + 4 <= end; j += 4) {
        int u0 = __ldg(&g_csr[j]);
        int u1 = __ldg(&g_csr[j + 1]);
        int u2 = __ldg(&g_csr[j + 2]);
        int u3 = __ldg(&g_csr[j + 3]);
        uint4 q0 = __ldg(&hb[u0 * 8 + c]);
        uint4 q1 = __ldg(&hb[u1 * 8 + c]);
        uint4 q2 = __ldg(&hb[u2 * 8 + c]);
        uint4 q3 = __ldg(&hb[u3 * 8 + c]);
        A0 = hadd2q(A0, q0);
        A1 = hadd2q(A1, q1);
        A2 = hadd2q(A2, q2);
        A3 = hadd2q(A3, q3);
    }
    for (; j < end; j++)
        A0 = hadd2q(A0, __ldg(&hb[__ldg(&g_csr[j]) * 8 + c]));

    A0 = hadd2q(hadd2q(A0, A1), hadd2q(A2, A3));
    reinterpret_cast<uint4*>(g_aggb)[v * 8 + c] = A0;
}

// ---------------------------------------------------------------------------
// HMMA MLP, 2-term (unchanged — measured, rel_err 0.0)
// ---------------------------------------------------------------------------
#define TILE_M 128
#define MLP_GRID ((N_NODES + TILE_M - 1) / TILE_M)   // 391

struct __align__(16) H2Smem {
    __nv_bfloat16 a[TILE_M * 64];
    __nv_bfloat16 bh[64 * 64];
    __nv_bfloat16 bl[64 * 64];
    float pool[DIM];
};

__device__ __forceinline__ uint32_t smem_u32(const void* p)
{
    uint32_t a;
    asm("{ .reg .u64 t; cvta.to.shared.u64 t, %1; cvt.u32.u64 %0, t; }"
        : "=r"(a) : "l"(p));
    return a;
}
__device__ __forceinline__ void ldsm4(uint32_t* r, uint32_t addr)
{
    asm volatile("ldmatrix.sync.aligned.m8n8.x4.shared.b16 {%0,%1,%2,%3}, [%4];"
                 : "=r"(r[0]), "=r"(r[1]), "=r"(r[2]), "=r"(r[3]) : "r"(addr));
}
__device__ __forceinline__ void ldsm2(uint32_t* r, uint32_t addr)
{
    asm volatile("ldmatrix.sync.aligned.m8n8.x2.shared.b16 {%0,%1}, [%2];"
                 : "=r"(r[0]), "=r"(r[1]) : "r"(addr));
}
__device__ __forceinline__ void mma16816(float* d, const uint32_t* a, const uint32_t* b)
{
    asm volatile("mma.sync.aligned.m16n8k16.row.col.f32.bf16.bf16.f32 "
                 "{%0,%1,%2,%3}, {%4,%5,%6,%7}, {%8,%9}, {%0,%1,%2,%3};"
                 : "+f"(d[0]), "+f"(d[1]), "+f"(d[2]), "+f"(d[3])
                 : "r"(a[0]), "r"(a[1]), "r"(a[2]), "r"(a[3]),
                   "r"(b[0]), "r"(b[1]));
}

__global__ __launch_bounds__(256) void k_mlp_h2(int layer)
{
    __shared__ H2Smem sm;

    int tid  = threadIdx.x;
    int lane = tid & 31;
    int w    = tid >> 5;
    int m0   = w * 16;
    int blockBase = blockIdx.x * TILE_M;

    char* a_c = reinterpret_cast<char*>(sm.a);

    {
        const uint4* agg4 = reinterpret_cast<const uint4*>(g_aggb);
#pragma unroll
        for (int r = 0; r < 4; r++) {
            int j = tid + 256 * r;
            int row = j >> 3, ch = j & 7;
            int node = blockBase + row;
            uint4 val = make_uint4(0, 0, 0, 0);
            if (node < N_NODES) val = __ldg(&agg4[node * 8 + ch]);
            uint32_t off = (uint32_t)row * 128 + ((uint32_t)(ch ^ (row & 7)) << 4);
            *reinterpret_cast<uint4*>(a_c + off) = val;
        }
    }
    if (tid < DIM) sm.pool[tid] = 0.f;

    uint32_t a_base  = smem_u32(sm.a);
    uint32_t bh_base = smem_u32(sm.bh);
    uint32_t bl_base = smem_u32(sm.bl);
    int r0 = m0 + (lane >> 2);
    int r1 = r0 + 8;

    for (int s = 0; s < 3; s++) {
        {
            const uint4* wh4 = reinterpret_cast<const uint4*>(
                g_wbh + (size_t)(layer * 3 + s) * 4096);
            const uint4* wl4 = reinterpret_cast<const uint4*>(
                g_wbl + (size_t)(layer * 3 + s) * 4096);
            uint4* sh = reinterpret_cast<uint4*>(sm.bh);
            uint4* sl = reinterpret_cast<uint4*>(sm.bl);
            sh[tid]       = __ldg(&wh4[tid]);
            sh[tid + 256] = __ldg(&wh4[tid + 256]);
            sl[tid]       = __ldg(&wl4[tid]);
            sl[tid + 256] = __ldg(&wl4[tid + 256]);
        }
        __syncthreads();

        float acc[8][4];
#pragma unroll
        for (int nt = 0; nt < 8; nt++)
#pragma unroll
            for (int q = 0; q < 4; q++) acc[nt][q] = 0.f;

#pragma unroll
        for (int kk = 0; kk < 4; kk++) {
            int arow = m0 + (lane & 15);
            uint32_t achunk = (uint32_t)(kk * 2 + (lane >> 4));
            uint32_t aoff = (uint32_t)arow * 128 + ((achunk ^ (arow & 7)) << 4);
            uint32_t aa[4];
            ldsm4(aa, a_base + aoff);

            int brow_l = lane & 7;
            uint32_t bchunk = (uint32_t)(kk * 2 + ((lane >> 3) & 1));
#pragma unroll
            for (int nt = 0; nt < 8; nt++) {
                int brow = nt * 8 + brow_l;
                uint32_t boff = (uint32_t)brow * 128 + ((bchunk ^ (brow & 7)) << 4);
                uint32_t bh[2], bl[2];
                ldsm2(bh, bh_base + boff);
                ldsm2(bl, bl_base + boff);
                mma16816(acc[nt], aa, bh);
                mma16816(acc[nt], aa, bl);
            }
        }
        __syncthreads();

        if (s < 2) {
#pragma unroll
            for (int nt = 0; nt < 8; nt++) {
                float v00 = fmaxf(acc[nt][0], 0.f);
                float v01 = fmaxf(acc[nt][1], 0.f);
                float v10 = fmaxf(acc[nt][2], 0.f);
                float v11 = fmaxf(acc[nt][3], 0.f);
                int p = nt * 4 + (lane & 3);
                uint32_t off0 = (uint32_t)r0 * 128 + (((uint32_t)(p >> 2) ^ (r0 & 7)) << 4) + (p & 3) * 4;
                uint32_t off1 = (uint32_t)r1 * 128 + (((uint32_t)(p >> 2) ^ (r1 & 7)) << 4) + (p & 3) * 4;
                *reinterpret_cast<uint32_t*>(a_c + off0) = pack_bf2(v00, v01);
                *reinterpret_cast<uint32_t*>(a_c + off1) = pack_bf2(v10, v11);
            }
            __syncthreads();
        } else {
            int node0 = blockBase + r0;
            int node1 = blockBase + r1;
            uint32_t* hb32 = reinterpret_cast<uint32_t*>(g_hb);
#pragma unroll
            for (int nt = 0; nt < 8; nt++) {
                float v00 = fmaxf(acc[nt][0], 0.f);
                float v01 = fmaxf(acc[nt][1], 0.f);
                float v10 = fmaxf(acc[nt][2], 0.f);
                float v11 = fmaxf(acc[nt][3], 0.f);
                int p = nt * 4 + (lane & 3);
                if (node0 < N_NODES) hb32[node0 * 32 + p] = pack_bf2(v00, v01);
                if (node1 < N_NODES) hb32[node1 * 32 + p] = pack_bf2(v10, v11);
                float s0 = v00 + v10, s1 = v01 + v11;
                s0 += __shfl_xor_sync(0xffffffffu, s0, 16);
                s0 += __shfl_xor_sync(0xffffffffu, s0, 8);
                s0 += __shfl_xor_sync(0xffffffffu, s0, 4);
                s1 += __shfl_xor_sync(0xffffffffu, s1, 16);
                s1 += __shfl_xor_sync(0xffffffffu, s1, 8);
                s1 += __shfl_xor_sync(0xffffffffu, s1, 4);
                if ((lane >> 2) == 0) {
                    int c0 = nt * 8 + (lane & 3) * 2;
                    atomicAdd(&sm.pool[c0],     s0);
                    atomicAdd(&sm.pool[c0 + 1], s1);
                }
            }
            __syncthreads();
            if (tid < DIM)
                atomicAdd(&g_pooled[layer * DIM + tid], sm.pool[tid]);
        }
    }
}

// ---------------------------------------------------------------------------
// Final: out = sigmoid( sum_l dot(pooled_l / N, Wl_l) ); re-zero g_pooled
// ---------------------------------------------------------------------------
__global__ void k_final(const float* __restrict__ Wl, float* __restrict__ out)
{
    __shared__ float red[128];
    int tid = threadIdx.x;
    float s = 0.0f;
    for (int i = tid; i < N_LAYERS * DIM; i += 128)
        s += g_pooled[i] * Wl[i];
    red[tid] = s;
    __syncthreads();
    for (int i = tid; i < N_LAYERS * DIM; i += 128)
        g_pooled[i] = 0.0f;
    for (int o = 64; o > 0; o >>= 1) {
        if (tid < o) red[tid] += red[tid + o];
        __syncthreads();
    }
    if (tid == 0) {
        float v = red[0] / (float)N_NODES;
        out[0] = 1.0f / (1.0f + expf(-v));
    }
}

// ---------------------------------------------------------------------------
// Launch
// ---------------------------------------------------------------------------
extern "C" void kernel_launch(void* const* d_in, const int* in_sizes, int n_in,
                              void* d_out, int out_size)
{
    const float* x   = (const float*)d_in[0];
    const float* W   = (const float*)d_in[1];
    const float* Wl  = (const float*)d_in[2];
    const int*   src = (const int*)d_in[3];
    const int*   dst = (const int*)d_in[4];
    float*       out = (float*)d_out;

    (void)in_sizes; (void)n_in; (void)out_size;

    k_count_x<<<(N_NODES * DIM / 2 + 255) / 256, 256>>>(dst, (const float2*)x); // idx0
    k_scan<<<SCAN_NBLK, SCAN_BLK>>>();                                          // idx1
    k_fill_w<<<(EQ + 255) / 256, 256>>>(src, dst, W);                           // idx2

    int gather_blocks = (N_NODES * 8 + 255) / 256;

    for (int l = 0; l < N_LAYERS; l++) {
        k_gather_b<<<gather_blocks, 256>>>();     // idx3 on first layer
        k_mlp_h2<<<MLP_GRID, 256>>>(l);
    }
    k_final<<<1, 128>>>(Wl, out);
}